// round 3
// baseline (speedup 1.0000x reference)
#include <cuda_runtime.h>
#include <cstdint>

// out[n, d, b] = unique_weights[indices[n], d] * input_values[n, d, b]
// N=16384, U=1024, D=128, B=16, fp32. Pure HBM-bound streaming multiply.
//
// One thread per even/odd d-pair (256 B): 1 idx load + 1 float2 weight load
// serve 8 float4 x-loads + 8 float4 stores. MLP=8, minimal overhead wavefronts.
// x / out use streaming (.cs) hints so the 256 MiB stream doesn't evict the
// L2-resident weight table.

#define N_POS 16384
#define U_DIM 1024
#define D_DIM 128
#define B_DIM 16

__global__ void __launch_bounds__(256) diag_scale_kernel(
    const float* __restrict__ x,          // [N, D, B]
    const float* __restrict__ w,          // [U, D]
    const int* __restrict__ idx,          // [N] (int32)
    float* __restrict__ out)              // [N, D, B]
{
    // One thread per pair of rows (n, 2dp) and (n, 2dp+1). 64 pairs per n.
    unsigned int pair = blockIdx.x * blockDim.x + threadIdx.x;   // over N*64
    if (pair >= (unsigned int)(N_POS * (D_DIM / 2))) return;

    unsigned int n  = pair >> 6;          // pair / 64
    unsigned int dp = pair & 63;          // pair % 64 -> d = 2*dp, 2*dp+1

    unsigned int u = (unsigned int)__ldg(&idx[n]) & (U_DIM - 1);
    float2 wv = __ldg(reinterpret_cast<const float2*>(&w[(size_t)u * D_DIM + 2 * dp]));

    const float4* __restrict__ xr = reinterpret_cast<const float4*>(x) + (size_t)pair * 8;
    float4* __restrict__ orow = reinterpret_cast<float4*>(out) + (size_t)pair * 8;

    // Front-batch 8 independent float4 streaming loads (MLP=8).
    float4 v0 = __ldcs(&xr[0]);
    float4 v1 = __ldcs(&xr[1]);
    float4 v2 = __ldcs(&xr[2]);
    float4 v3 = __ldcs(&xr[3]);
    float4 v4 = __ldcs(&xr[4]);
    float4 v5 = __ldcs(&xr[5]);
    float4 v6 = __ldcs(&xr[6]);
    float4 v7 = __ldcs(&xr[7]);

    float wa = wv.x, wb = wv.y;
    v0.x *= wa; v0.y *= wa; v0.z *= wa; v0.w *= wa;
    v1.x *= wa; v1.y *= wa; v1.z *= wa; v1.w *= wa;
    v2.x *= wa; v2.y *= wa; v2.z *= wa; v2.w *= wa;
    v3.x *= wa; v3.y *= wa; v3.z *= wa; v3.w *= wa;
    v4.x *= wb; v4.y *= wb; v4.z *= wb; v4.w *= wb;
    v5.x *= wb; v5.y *= wb; v5.z *= wb; v5.w *= wb;
    v6.x *= wb; v6.y *= wb; v6.z *= wb; v6.w *= wb;
    v7.x *= wb; v7.y *= wb; v7.z *= wb; v7.w *= wb;

    __stcs(&orow[0], v0);
    __stcs(&orow[1], v1);
    __stcs(&orow[2], v2);
    __stcs(&orow[3], v3);
    __stcs(&orow[4], v4);
    __stcs(&orow[5], v5);
    __stcs(&orow[6], v6);
    __stcs(&orow[7], v7);
}

extern "C" void kernel_launch(void* const* d_in, const int* in_sizes, int n_in,
                              void* d_out, int out_size)
{
    // Bind by element count — robust to metadata ordering.
    const float* x = nullptr;    // N*D*B = 33,554,432
    const float* w = nullptr;    // U*D   = 131,072
    const int* idx = nullptr;    // N     = 16,384
    for (int i = 0; i < n_in; i++) {
        if (in_sizes[i] == N_POS * D_DIM * B_DIM)   x   = (const float*)d_in[i];
        else if (in_sizes[i] == U_DIM * D_DIM)      w   = (const float*)d_in[i];
        else if (in_sizes[i] == N_POS)              idx = (const int*)d_in[i];
    }
    float* out = (float*)d_out;

    const int pairs = N_POS * (D_DIM / 2);   // 1,048,576
    const int threads = 256;
    const int blocks = (pairs + threads - 1) / threads;

    diag_scale_kernel<<<blocks, threads>>>(x, w, idx, out);
}

// round 4
// speedup vs baseline: 1.4687x; 1.4687x over previous
#include <cuda_runtime.h>
#include <cstdint>

// out[n, d, b] = unique_weights[indices[n], d] * input_values[n, d, b]
// N=16384, U=1024, D=128, B=16, fp32. Pure HBM-bound streaming multiply.
//
// R2 structure (known 44.3us): one thread per (n,d) row, 4x float4, 28 regs,
// occ ~80%. Single isolated change vs R2: __ldcs on the x stream only
// (evict-first so 128 MiB x stream doesn't evict the L2-resident weight
// table). Stores are plain STG.

#define N_POS 16384
#define U_DIM 1024
#define D_DIM 128
#define B_DIM 16

__global__ void __launch_bounds__(256) diag_scale_kernel(
    const float* __restrict__ x,          // [N, D, B]
    const float* __restrict__ w,          // [U, D]
    const int* __restrict__ idx,          // [N] (int32)
    float* __restrict__ out)              // [N, D, B]
{
    unsigned int row = blockIdx.x * blockDim.x + threadIdx.x;  // over N*D rows
    if (row >= (unsigned int)(N_POS * D_DIM)) return;

    unsigned int n = row >> 7;            // row / 128
    unsigned int d = row & 127;           // row % 128

    unsigned int u = (unsigned int)__ldg(&idx[n]) & (U_DIM - 1);
    float wv = __ldg(&w[(size_t)u * D_DIM + d]);

    const float4* __restrict__ xr = reinterpret_cast<const float4*>(x) + (size_t)row * 4;
    float4* __restrict__ orow = reinterpret_cast<float4*>(out) + (size_t)row * 4;

    // Front-batch the 4 independent float4 loads (MLP=4), streaming hint.
    float4 v0 = __ldcs(&xr[0]);
    float4 v1 = __ldcs(&xr[1]);
    float4 v2 = __ldcs(&xr[2]);
    float4 v3 = __ldcs(&xr[3]);

    v0.x *= wv; v0.y *= wv; v0.z *= wv; v0.w *= wv;
    v1.x *= wv; v1.y *= wv; v1.z *= wv; v1.w *= wv;
    v2.x *= wv; v2.y *= wv; v2.z *= wv; v2.w *= wv;
    v3.x *= wv; v3.y *= wv; v3.z *= wv; v3.w *= wv;

    orow[0] = v0;
    orow[1] = v1;
    orow[2] = v2;
    orow[3] = v3;
}

extern "C" void kernel_launch(void* const* d_in, const int* in_sizes, int n_in,
                              void* d_out, int out_size)
{
    // Bind by element count — robust to metadata ordering.
    const float* x = nullptr;    // N*D*B = 33,554,432
    const float* w = nullptr;    // U*D   = 131,072
    const int* idx = nullptr;    // N     = 16,384
    for (int i = 0; i < n_in; i++) {
        if (in_sizes[i] == N_POS * D_DIM * B_DIM)   x   = (const float*)d_in[i];
        else if (in_sizes[i] == U_DIM * D_DIM)      w   = (const float*)d_in[i];
        else if (in_sizes[i] == N_POS)              idx = (const int*)d_in[i];
    }
    float* out = (float*)d_out;

    const int rows = N_POS * D_DIM;       // 2,097,152
    const int threads = 256;
    const int blocks = (rows + threads - 1) / threads;

    diag_scale_kernel<<<blocks, threads>>>(x, w, idx, out);
}

// round 5
// speedup vs baseline: 1.5070x; 1.0261x over previous
#include <cuda_runtime.h>
#include <cstdint>

// out[n, d, b] = unique_weights[indices[n], d] * input_values[n, d, b]
// N=16384, U=1024, D=128, B=16, fp32. Pure HBM-bound streaming multiply.
//
// R2 structure (best known: 44.3us kernel, DRAM 61.8%): one thread per (n,d)
// row, 4x float4, plain LDG/STG (.cs hints proven harmful in R3/R4).
// Single change vs R2: block 512, exact-divide grid, no bounds branch.

#define N_POS 16384
#define U_DIM 1024
#define D_DIM 128
#define B_DIM 16

__global__ void __launch_bounds__(512) diag_scale_kernel(
    const float* __restrict__ x,          // [N, D, B]
    const float* __restrict__ w,          // [U, D]
    const int* __restrict__ idx,          // [N] (int32)
    float* __restrict__ out)              // [N, D, B]
{
    unsigned int row = blockIdx.x * blockDim.x + threadIdx.x;  // over N*D rows

    unsigned int n = row >> 7;            // row / 128
    unsigned int d = row & 127;           // row % 128

    unsigned int u = (unsigned int)__ldg(&idx[n]) & (U_DIM - 1);
    float wv = __ldg(&w[(size_t)u * D_DIM + d]);

    const float4* __restrict__ xr = reinterpret_cast<const float4*>(x) + (size_t)row * 4;
    float4* __restrict__ orow = reinterpret_cast<float4*>(out) + (size_t)row * 4;

    // Front-batch the 4 independent float4 loads (MLP=4).
    float4 v0 = __ldg(&xr[0]);
    float4 v1 = __ldg(&xr[1]);
    float4 v2 = __ldg(&xr[2]);
    float4 v3 = __ldg(&xr[3]);

    v0.x *= wv; v0.y *= wv; v0.z *= wv; v0.w *= wv;
    v1.x *= wv; v1.y *= wv; v1.z *= wv; v1.w *= wv;
    v2.x *= wv; v2.y *= wv; v2.z *= wv; v2.w *= wv;
    v3.x *= wv; v3.y *= wv; v3.z *= wv; v3.w *= wv;

    orow[0] = v0;
    orow[1] = v1;
    orow[2] = v2;
    orow[3] = v3;
}

extern "C" void kernel_launch(void* const* d_in, const int* in_sizes, int n_in,
                              void* d_out, int out_size)
{
    // Bind by element count — robust to metadata ordering.
    const float* x = nullptr;    // N*D*B = 33,554,432
    const float* w = nullptr;    // U*D   = 131,072
    const int* idx = nullptr;    // N     = 16,384
    for (int i = 0; i < n_in; i++) {
        if (in_sizes[i] == N_POS * D_DIM * B_DIM)   x   = (const float*)d_in[i];
        else if (in_sizes[i] == U_DIM * D_DIM)      w   = (const float*)d_in[i];
        else if (in_sizes[i] == N_POS)              idx = (const int*)d_in[i];
    }
    float* out = (float*)d_out;

    const int rows = N_POS * D_DIM;       // 2,097,152
    const int threads = 512;
    const int blocks = rows / threads;    // 4096, exact

    diag_scale_kernel<<<blocks, threads>>>(x, w, idx, out);
}